// round 14
// baseline (speedup 1.0000x reference)
#include <cuda_runtime.h>
#include <cuda_bf16.h>
#include <math.h>
#include <cstdint>

#define T_DIM 4
#define B_DIM 32
#define N_DIM 2048
#define H_DIM 512
#define KB_DIM 512

// ---------------- device scratch (no allocations) ----------------
__device__ __align__(16) float g_projmem[B_DIM * H_DIM];
__device__ __align__(16) float g_logits[B_DIM * N_DIM];
__device__ __align__(16) float g_a[B_DIM * N_DIM];
__device__ __align__(16) float g_cb[B_DIM * H_DIM];      // folded bias per batch

__device__ __align__(16) __nv_bfloat16 g_Ahi[(size_t)B_DIM * N_DIM * KB_DIM];
__device__ __align__(16) __nv_bfloat16 g_Alo[(size_t)B_DIM * N_DIM * KB_DIM];
__device__ __align__(16) __nv_bfloat16 g_H2hi[(size_t)B_DIM * N_DIM * H_DIM];
__device__ __align__(16) __nv_bfloat16 g_H2lo[(size_t)B_DIM * N_DIM * H_DIM];
__device__ __align__(16) __nv_bfloat16 g_WkbThi[KB_DIM * H_DIM];   // W_kb^T [kk][h]
__device__ __align__(16) __nv_bfloat16 g_WkbTlo[KB_DIM * H_DIM];
__device__ __align__(16) __nv_bfloat16 g_W2hi[H_DIM * H_DIM];
__device__ __align__(16) __nv_bfloat16 g_W2lo[H_DIM * H_DIM];
__device__ __align__(16) __nv_bfloat16 g_Wchi[(size_t)B_DIM * H_DIM * H_DIM];
__device__ __align__(16) __nv_bfloat16 g_Wclo[(size_t)B_DIM * H_DIM * H_DIM];
__device__ __align__(16) __nv_bfloat16 g_Mhi[(size_t)B_DIM * H_DIM * KB_DIM];  // folded weight
__device__ __align__(16) __nv_bfloat16 g_Mlo[(size_t)B_DIM * H_DIM * KB_DIM];

// ---------------- helpers (baseline ISA only) ----------------
__device__ __forceinline__ uint32_t smem_to_u32(const void* p) {
    uint32_t a;
    asm("{ .reg .u64 t; cvta.to.shared.u64 t, %1; cvt.u32.u64 %0, t; }" : "=r"(a) : "l"(p));
    return a;
}
#define CP_ASYNC(dst, src) \
    asm volatile("cp.async.cg.shared.global [%0], [%1], 16;" :: "r"(dst), "l"(src) : "memory")
#define CP_COMMIT() asm volatile("cp.async.commit_group;" ::: "memory")
#define CP_WAIT(n)  asm volatile("cp.async.wait_group %0;" :: "n"(n) : "memory")

__device__ __forceinline__ void ldsm4(uint32_t* r, uint32_t addr) {
    asm volatile("ldmatrix.sync.aligned.m8n8.x4.shared.b16 {%0,%1,%2,%3}, [%4];"
                 : "=r"(r[0]), "=r"(r[1]), "=r"(r[2]), "=r"(r[3]) : "r"(addr));
}
__device__ __forceinline__ void mma_bf16(float* c, const uint32_t* a, const uint32_t* b) {
    asm volatile(
        "mma.sync.aligned.m16n8k16.row.col.f32.bf16.bf16.f32 "
        "{%0,%1,%2,%3}, {%4,%5,%6,%7}, {%8,%9}, {%0,%1,%2,%3};"
        : "+f"(c[0]), "+f"(c[1]), "+f"(c[2]), "+f"(c[3])
        : "r"(a[0]), "r"(a[1]), "r"(a[2]), "r"(a[3]), "r"(b[0]), "r"(b[1]));
}
__device__ __forceinline__ void split2(float x, __nv_bfloat16& h, __nv_bfloat16& l) {
    h = __float2bfloat16(x);
    l = __float2bfloat16(x - __bfloat162float(h));
}
__device__ __forceinline__ float warp_sum(float v) {
    #pragma unroll
    for (int o = 16; o > 0; o >>= 1) v += __shfl_xor_sync(0xffffffffu, v, o);
    return v;
}

// ---------------- transpose+split know[b][kk][n] -> A[b][n][kk] hi/lo ----------------
__global__ void k_convT(const float* __restrict__ know) {
    __shared__ float t[32][33];
    int b = blockIdx.z;
    int n0 = blockIdx.x * 32, k0 = blockIdx.y * 32;
    int tx = threadIdx.x & 31, ty = threadIdx.x >> 5;
    const float* src = know + ((size_t)b * KB_DIM + k0) * (size_t)N_DIM + n0;
    #pragma unroll
    for (int i = 0; i < 4; i++) {
        int kk = ty + i * 8;
        t[kk][tx] = src[(size_t)kk * N_DIM + tx];
    }
    __syncthreads();
    #pragma unroll
    for (int i = 0; i < 4; i++) {
        int n = ty + i * 8;
        float v = t[tx][n];
        __nv_bfloat16 h, l;
        split2(v, h, l);
        size_t o = ((size_t)b * N_DIM + n0 + n) * KB_DIM + k0 + tx;
        g_Ahi[o] = h;
        g_Alo[o] = l;
    }
}

// ---------------- K0: proj_mem; also init g_cb=b_cat and zero g_logits ----------------
__global__ void k_projmem(const float* __restrict__ memory, const float* __restrict__ masks,
                          const float* __restrict__ W_mem, const float* __restrict__ b_mem,
                          const float* __restrict__ b_cat) {
    int b = blockIdx.x;
    int t = threadIdx.x;
    g_cb[b * H_DIM + t] = b_cat[t];
    #pragma unroll
    for (int i = 0; i < 4; i++) g_logits[b * N_DIM + t * 4 + i] = 0.f;
    __shared__ float lm[H_DIM];
    lm[t] = memory[((T_DIM - 1) * B_DIM + b) * H_DIM + t] * masks[b * H_DIM + t];
    __syncthreads();
    const float* w = W_mem + t * H_DIM;
    float s = 0.f;
    #pragma unroll 8
    for (int j = 0; j < H_DIM; j++) s = fmaf(lm[j], w[j], s);
    g_projmem[b * H_DIM + t] = s + b_mem[t];
}

// ---------------- K1: folded Wc -> bf16 hi/lo; also accumulate cb += b_kb.Wc ----------
__global__ void k_wc_split(const float* __restrict__ W_cat, const float* __restrict__ b_kb) {
    int idx = blockIdx.x * 256 + threadIdx.x;          // over B*H*H
    int h = idx & 511;
    int g = (idx >> 9) & 511;
    int b = idx >> 18;
    float w = fmaf(W_cat[g * (2 * H_DIM) + h], g_projmem[b * H_DIM + h],
                   W_cat[g * (2 * H_DIM) + H_DIM + h]);
    __nv_bfloat16 hi, lo;
    split2(w, hi, lo);
    g_Wchi[idx] = hi;
    g_Wclo[idx] = lo;
    float s = warp_sum(b_kb[h] * w);
    if ((threadIdx.x & 31) == 0) atomicAdd(&g_cb[(b << 9) + g], s);
}

// ---------------- transpose+split W_kb [h][kk] -> W_kbT [kk][h] hi/lo ----------------
__global__ void k_split_wkbT(const float* __restrict__ W_kb) {
    __shared__ float t[32][33];
    int kk0 = blockIdx.x * 32, h0 = blockIdx.y * 32;
    int tx = threadIdx.x & 31, ty = threadIdx.x >> 5;
    #pragma unroll
    for (int i = 0; i < 4; i++) {
        int h = ty + i * 8;
        t[h][tx] = W_kb[(size_t)(h0 + h) * KB_DIM + kk0 + tx];
    }
    __syncthreads();
    #pragma unroll
    for (int i = 0; i < 4; i++) {
        int kk = ty + i * 8;
        float v = t[tx][kk];
        __nv_bfloat16 h, l;
        split2(v, h, l);
        size_t o = (size_t)(kk0 + kk) * H_DIM + h0 + tx;
        g_WkbThi[o] = h;
        g_WkbTlo[o] = l;
    }
}

// ---------------- weight split W_cat2 ----------------
__global__ void k_split_w2(const float* __restrict__ src) {
    int i = blockIdx.x * 256 + threadIdx.x;            // over H*H
    __nv_bfloat16 h, l;
    split2(src[i], h, l);
    g_W2hi[i] = h;
    g_W2lo[i] = l;
}

// ---------------- HMMA GEMM: CTA 128x128, BK=16, double-buffered cp.async + ldmatrix ----
// C[m][n] = sum_k A[m][k]*B[n][k]   (bf16 hi/lo, 3 passes, fp32 acc)
// 8 warps: 4 in m (32 rows each) x 2 in n (64 cols each); acc 2x8x4.
// MODE 4: A=g_Wc[b],  B=g_WkbT,  no bias       -> split g_M[b]
// MODE 2: A=g_A[b],   B=g_M[b],  +g_cb, ELU    -> split g_H2[b]
// MODE 3: A=g_H2[b],  B=g_W2,    +b_cat2       -> fused elu(h2*ctl)*W_attn -> atomic g_logits
// Stage (48B padded rows): Ah[128] @0, Al @6144, Bh[128] @12288, Bl @18432. 24576 B/stage.
#define STAGE_BYTES 24576

template <int MODE>
__global__ __launch_bounds__(256, 1)
void kg(const float* __restrict__ bias_ext, const float* __restrict__ control,
        const float* __restrict__ W_attn) {
    __shared__ __align__(16) char smem[2 * STAGE_BYTES];
    const uint32_t sb = smem_to_u32(smem);
    const int tid = threadIdx.x, lane = tid & 31, wid = tid >> 5;
    const int m0 = blockIdx.x * 128, n0 = blockIdx.y * 128, b = blockIdx.z;

    const __nv_bfloat16 *Ahi, *Alo, *Bhi, *Blo;
    if (MODE == 4) {
        Ahi = g_Wchi + (size_t)b * H_DIM * H_DIM;  Alo = g_Wclo + (size_t)b * H_DIM * H_DIM;
        Bhi = g_WkbThi;  Blo = g_WkbTlo;
    } else if (MODE == 2) {
        Ahi = g_Ahi + (size_t)b * N_DIM * KB_DIM;  Alo = g_Alo + (size_t)b * N_DIM * KB_DIM;
        Bhi = g_Mhi + (size_t)b * H_DIM * KB_DIM;  Blo = g_Mlo + (size_t)b * H_DIM * KB_DIM;
    } else {
        Ahi = g_H2hi + (size_t)b * N_DIM * H_DIM;  Alo = g_H2lo + (size_t)b * N_DIM * H_DIM;
        Bhi = g_W2hi;  Blo = g_W2lo;
    }

    auto issue = [&](int s) {
        const uint32_t base = sb + (uint32_t)(s & 1) * STAGE_BYTES;
        const int kk0 = s * 16;
        const int r = tid >> 1, c = tid & 1;
        {
            uint32_t d = base + r * 48 + c * 16;                 // A: 128 rows x 2 chunks
            size_t go = (size_t)(m0 + r) * 512 + kk0 + c * 8;
            CP_ASYNC(d, Ahi + go);
            CP_ASYNC(d + 6144, Alo + go);
        }
        {
            uint32_t d = base + 12288 + r * 48 + c * 16;         // B: 128 rows x 2 chunks
            size_t go = (size_t)(n0 + r) * 512 + kk0 + c * 8;
            CP_ASYNC(d, Bhi + go);
            CP_ASYNC(d + 6144, Blo + go);
        }
        CP_COMMIT();
    };

    float acc[2][8][4] = {};
    const int mb = (wid & 3) * 32;       // 4 warps in m
    const int nb = (wid >> 2) * 64;      // 2 warps in n (64 cols each)

    issue(0);
    for (int s = 0; s < 32; s++) {
        if (s < 31) { issue(s + 1); CP_WAIT(1); }
        else        { CP_WAIT(0); }
        __syncthreads();
        const uint32_t cb = sb + (uint32_t)(s & 1) * STAGE_BYTES;
        const uint32_t aAddr = cb + (mb + (lane & 15)) * 48 + ((lane >> 4) << 4);
        const uint32_t bAddr = cb + 12288 +
            (nb + ((lane >> 4) << 3) + (lane & 7)) * 48 + (((lane >> 3) & 1) << 4);
        uint32_t ah[2][4], al[2][4], bh[4][4], bl[4][4];
        ldsm4(ah[0], aAddr);
        ldsm4(ah[1], aAddr + 16 * 48);
        ldsm4(al[0], aAddr + 6144);
        ldsm4(al[1], aAddr + 6144 + 16 * 48);
        #pragma unroll
        for (int i = 0; i < 4; i++) {
            ldsm4(bh[i], bAddr + i * 16 * 48);                   // n-frags 2i, 2i+1
            ldsm4(bl[i], bAddr + 6144 + i * 16 * 48);
        }
        #pragma unroll
        for (int mf = 0; mf < 2; mf++) {
            #pragma unroll
            for (int nf = 0; nf < 8; nf++) {
                const uint32_t* BH = &bh[nf >> 1][(nf & 1) * 2];
                const uint32_t* BL = &bl[nf >> 1][(nf & 1) * 2];
                mma_bf16(acc[mf][nf], ah[mf], BH);
                mma_bf16(acc[mf][nf], ah[mf], BL);
                mma_bf16(acc[mf][nf], al[mf], BH);
            }
        }
        __syncthreads();
    }

    const int gr = lane >> 2, gc = (lane & 3) * 2;

    if (MODE == 3) {
        // fused: logits[b,row] += sum_col elu((acc+bias)*ctl[col]) * W_attn[col]
        const float* ctl = control + ((T_DIM - 1) * B_DIM + b) * H_DIM;
        float part[2][2] = {};
        #pragma unroll
        for (int nf = 0; nf < 8; nf++) {
            int col = n0 + nb + nf * 8 + gc;
            float bv0 = __ldg(bias_ext + col), bv1 = __ldg(bias_ext + col + 1);
            float c0 = __ldg(ctl + col), c1 = __ldg(ctl + col + 1);
            float w0 = __ldg(W_attn + col), w1 = __ldg(W_attn + col + 1);
            #pragma unroll
            for (int mf = 0; mf < 2; mf++) {
                #pragma unroll
                for (int h = 0; h < 2; h++) {
                    float x0 = (acc[mf][nf][h * 2 + 0] + bv0) * c0;
                    float x1 = (acc[mf][nf][h * 2 + 1] + bv1) * c1;
                    x0 = (x0 > 0.f) ? x0 : expm1f(x0);
                    x1 = (x1 > 0.f) ? x1 : expm1f(x1);
                    part[mf][h] = fmaf(x0, w0, part[mf][h]);
                    part[mf][h] = fmaf(x1, w1, part[mf][h]);
                }
            }
        }
        #pragma unroll
        for (int mf = 0; mf < 2; mf++) {
            #pragma unroll
            for (int h = 0; h < 2; h++) {
                float r = part[mf][h];
                r += __shfl_xor_sync(0xffffffffu, r, 1);
                r += __shfl_xor_sync(0xffffffffu, r, 2);
                if ((lane & 3) == 0) {
                    int row = m0 + mb + mf * 16 + gr + h * 8;
                    atomicAdd(&g_logits[b * N_DIM + row], r);
                }
            }
        }
        return;
    }

    const float* bias = g_cb + b * H_DIM;
    #pragma unroll
    for (int mf = 0; mf < 2; mf++) {
        #pragma unroll
        for (int nf = 0; nf < 8; nf++) {
            int col = n0 + nb + nf * 8 + gc;
            float bv0 = 0.f, bv1 = 0.f;
            if (MODE == 2) { bv0 = __ldg(bias + col); bv1 = __ldg(bias + col + 1); }
            #pragma unroll
            for (int h = 0; h < 2; h++) {
                int row = m0 + mb + mf * 16 + gr + h * 8;
                float v0 = acc[mf][nf][h * 2 + 0] + bv0;
                float v1 = acc[mf][nf][h * 2 + 1] + bv1;
                if (MODE == 2) {
                    v0 = (v0 > 0.f) ? v0 : expm1f(v0);
                    v1 = (v1 > 0.f) ? v1 : expm1f(v1);
                }
                size_t o = ((size_t)b * ((MODE == 4) ? H_DIM : N_DIM) + row) * 512 + col;
                __nv_bfloat16 h0, l0, h1, l1;
                split2(v0, h0, l0);
                split2(v1, h1, l1);
                __nv_bfloat162 hv; hv.x = h0; hv.y = h1;
                __nv_bfloat162 lv; lv.x = l0; lv.y = l1;
                if (MODE == 4) {
                    *(__nv_bfloat162*)(g_Mhi + o) = hv;
                    *(__nv_bfloat162*)(g_Mlo + o) = lv;
                } else {
                    *(__nv_bfloat162*)(g_H2hi + o) = hv;
                    *(__nv_bfloat162*)(g_H2lo + o) = lv;
                }
            }
        }
    }
}

// ---------------- softmax / read ----------------
__global__ void k_softmax() {
    int b = blockIdx.x;
    int t = threadIdx.x;
    __shared__ float red[256];
    float m = -1e30f;
    for (int i = t; i < N_DIM; i += 256) m = fmaxf(m, g_logits[b * N_DIM + i]);
    red[t] = m;
    __syncthreads();
    for (int s = 128; s > 0; s >>= 1) {
        if (t < s) red[t] = fmaxf(red[t], red[t + s]);
        __syncthreads();
    }
    m = red[0];
    __syncthreads();
    float sum = 0.f;
    for (int i = t; i < N_DIM; i += 256) {
        float e = expf(g_logits[b * N_DIM + i] - m);
        g_a[b * N_DIM + i] = e;
        sum += e;
    }
    red[t] = sum;
    __syncthreads();
    for (int s = 128; s > 0; s >>= 1) {
        if (t < s) red[t] += red[t + s];
        __syncthreads();
    }
    float inv = 1.f / red[0];
    for (int i = t; i < N_DIM; i += 256) g_a[b * N_DIM + i] *= inv;
}

__global__ void k_read(const float* __restrict__ know, float* __restrict__ out) {
    int b = blockIdx.y;
    __shared__ __align__(16) float a_sh[N_DIM];
    for (int i = threadIdx.x; i < N_DIM; i += 256) a_sh[i] = g_a[b * N_DIM + i];
    __syncthreads();
    int warp = threadIdx.x >> 5, lane = threadIdx.x & 31;
    int kk = blockIdx.x * 8 + warp;
    const float* kr = know + ((size_t)b * KB_DIM + kk) * N_DIM;
    float s = 0.f;
    #pragma unroll
    for (int it = 0; it < 16; it++) {
        int n = it * 128 + lane * 4;
        float4 v = *(const float4*)(kr + n);
        float4 a = *(const float4*)&a_sh[n];
        s = fmaf(v.x, a.x, s);
        s = fmaf(v.y, a.y, s);
        s = fmaf(v.z, a.z, s);
        s = fmaf(v.w, a.w, s);
    }
    s = warp_sum(s);
    if (lane == 0) out[b * KB_DIM + kk] = s;
}

// ---------------- launch (ordered so kg<2> is launch #6 for ncu -s 5 -c 1) -------------
extern "C" void kernel_launch(void* const* d_in, const int* in_sizes, int n_in,
                              void* d_out, int out_size) {
    const float* memory  = (const float*)d_in[0];
    const float* know    = (const float*)d_in[1];
    const float* control = (const float*)d_in[2];
    const float* masks   = (const float*)d_in[3];
    const float* W_mem   = (const float*)d_in[4];
    const float* b_mem   = (const float*)d_in[5];
    const float* W_kb    = (const float*)d_in[6];
    const float* b_kb    = (const float*)d_in[7];
    const float* W_cat   = (const float*)d_in[8];
    const float* b_cat   = (const float*)d_in[9];
    const float* W_cat2  = (const float*)d_in[10];
    const float* b_cat2  = (const float*)d_in[11];
    const float* W_attn  = (const float*)d_in[12];
    float* out = (float*)d_out;

    k_convT<<<dim3(N_DIM / 32, KB_DIM / 32, B_DIM), 256>>>(know);            // 1
    k_projmem<<<B_DIM, 512>>>(memory, masks, W_mem, b_mem, b_cat);           // 2
    k_wc_split<<<(B_DIM * H_DIM * H_DIM) / 256, 256>>>(W_cat, b_kb);         // 3
    k_split_wkbT<<<dim3(KB_DIM / 32, H_DIM / 32), 256>>>(W_kb);              // 4
    // weight fold: M_b = Wc_b @ W_kb   (512x512, K=512, per batch)
    kg<4><<<dim3(H_DIM / 128, H_DIM / 128, B_DIM), 256>>>(nullptr, nullptr, nullptr);   // 5
    // h = elu(k @ M_b^T + c_b)
    kg<2><<<dim3(N_DIM / 128, H_DIM / 128, B_DIM), 256>>>(nullptr, nullptr, nullptr);   // 6 <- ncu
    k_split_w2<<<(H_DIM * H_DIM) / 256, 256>>>(W_cat2);                      // 7
    // logits += sum_g elu((h @ W2^T + b_cat2) * ctl) * W_attn   (fused)
    kg<3><<<dim3(N_DIM / 128, H_DIM / 128, B_DIM), 256>>>(b_cat2, control, W_attn);     // 8
    k_softmax<<<B_DIM, 256>>>();                                             // 9
    k_read<<<dim3(KB_DIM / 8, B_DIM), 256>>>(know, out);                     // 10
}

// round 15
// speedup vs baseline: 1.1323x; 1.1323x over previous
#include <cuda_runtime.h>
#include <cuda_fp16.h>
#include <math.h>
#include <cstdint>

#define T_DIM 4
#define B_DIM 32
#define N_DIM 2048
#define H_DIM 512
#define KB_DIM 512

// ---------------- device scratch (no allocations) ----------------
__device__ __align__(16) float g_projmem[B_DIM * H_DIM];
__device__ __align__(16) float g_logits[B_DIM * N_DIM];
__device__ __align__(16) float g_a[B_DIM * N_DIM];
__device__ __align__(16) float g_cb[B_DIM * H_DIM];      // folded bias per batch

__device__ __align__(16) __half g_Ahi[(size_t)B_DIM * N_DIM * KB_DIM];
__device__ __align__(16) __half g_Alo[(size_t)B_DIM * N_DIM * KB_DIM];
__device__ __align__(16) __half g_H2hi[(size_t)B_DIM * N_DIM * H_DIM];
__device__ __align__(16) __half g_H2lo[(size_t)B_DIM * N_DIM * H_DIM];
__device__ __align__(16) __half g_WkbThi[KB_DIM * H_DIM];   // W_kb^T [kk][h]
__device__ __align__(16) __half g_WkbTlo[KB_DIM * H_DIM];
__device__ __align__(16) __half g_W2hi[H_DIM * H_DIM];
__device__ __align__(16) __half g_W2lo[H_DIM * H_DIM];
__device__ __align__(16) __half g_Wchi[(size_t)B_DIM * H_DIM * H_DIM];
__device__ __align__(16) __half g_Wclo[(size_t)B_DIM * H_DIM * H_DIM];
__device__ __align__(16) __half g_Mhi[(size_t)B_DIM * H_DIM * KB_DIM];  // folded weight
__device__ __align__(16) __half g_Mlo[(size_t)B_DIM * H_DIM * KB_DIM];

// ---------------- helpers (baseline ISA only) ----------------
__device__ __forceinline__ uint32_t smem_to_u32(const void* p) {
    uint32_t a;
    asm("{ .reg .u64 t; cvta.to.shared.u64 t, %1; cvt.u32.u64 %0, t; }" : "=r"(a) : "l"(p));
    return a;
}
#define CP_ASYNC(dst, src) \
    asm volatile("cp.async.cg.shared.global [%0], [%1], 16;" :: "r"(dst), "l"(src) : "memory")
#define CP_COMMIT() asm volatile("cp.async.commit_group;" ::: "memory")
#define CP_WAIT(n)  asm volatile("cp.async.wait_group %0;" :: "n"(n) : "memory")

__device__ __forceinline__ void ldsm4(uint32_t* r, uint32_t addr) {
    asm volatile("ldmatrix.sync.aligned.m8n8.x4.shared.b16 {%0,%1,%2,%3}, [%4];"
                 : "=r"(r[0]), "=r"(r[1]), "=r"(r[2]), "=r"(r[3]) : "r"(addr));
}
__device__ __forceinline__ void mma_f16(float* c, const uint32_t* a, const uint32_t* b) {
    asm volatile(
        "mma.sync.aligned.m16n8k16.row.col.f32.f16.f16.f32 "
        "{%0,%1,%2,%3}, {%4,%5,%6,%7}, {%8,%9}, {%0,%1,%2,%3};"
        : "+f"(c[0]), "+f"(c[1]), "+f"(c[2]), "+f"(c[3])
        : "r"(a[0]), "r"(a[1]), "r"(a[2]), "r"(a[3]), "r"(b[0]), "r"(b[1]));
}
__device__ __forceinline__ void split2(float x, __half& h, __half& l) {
    h = __float2half(x);
    l = __float2half(x - __half2float(h));
}
__device__ __forceinline__ float warp_sum(float v) {
    #pragma unroll
    for (int o = 16; o > 0; o >>= 1) v += __shfl_xor_sync(0xffffffffu, v, o);
    return v;
}

// ---------------- transpose+split know[b][kk][n] -> A[b][n][kk] hi/lo ----------------
__global__ void k_convT(const float* __restrict__ know) {
    __shared__ float t[32][33];
    int b = blockIdx.z;
    int n0 = blockIdx.x * 32, k0 = blockIdx.y * 32;
    int tx = threadIdx.x & 31, ty = threadIdx.x >> 5;
    const float* src = know + ((size_t)b * KB_DIM + k0) * (size_t)N_DIM + n0;
    #pragma unroll
    for (int i = 0; i < 4; i++) {
        int kk = ty + i * 8;
        t[kk][tx] = src[(size_t)kk * N_DIM + tx];
    }
    __syncthreads();
    #pragma unroll
    for (int i = 0; i < 4; i++) {
        int n = ty + i * 8;
        float v = t[tx][n];
        __half h, l;
        split2(v, h, l);
        size_t o = ((size_t)b * N_DIM + n0 + n) * KB_DIM + k0 + tx;
        g_Ahi[o] = h;
        g_Alo[o] = l;
    }
}

// ---------------- K0: proj_mem; also init g_cb=b_cat and zero g_logits ----------------
__global__ void k_projmem(const float* __restrict__ memory, const float* __restrict__ masks,
                          const float* __restrict__ W_mem, const float* __restrict__ b_mem,
                          const float* __restrict__ b_cat) {
    int b = blockIdx.x;
    int t = threadIdx.x;
    g_cb[b * H_DIM + t] = b_cat[t];
    #pragma unroll
    for (int i = 0; i < 4; i++) g_logits[b * N_DIM + t * 4 + i] = 0.f;
    __shared__ float lm[H_DIM];
    lm[t] = memory[((T_DIM - 1) * B_DIM + b) * H_DIM + t] * masks[b * H_DIM + t];
    __syncthreads();
    const float* w = W_mem + t * H_DIM;
    float s = 0.f;
    #pragma unroll 8
    for (int j = 0; j < H_DIM; j++) s = fmaf(lm[j], w[j], s);
    g_projmem[b * H_DIM + t] = s + b_mem[t];
}

// ---------------- K1: folded Wc -> fp16 hi/lo; also accumulate cb += b_kb.Wc ----------
__global__ void k_wc_split(const float* __restrict__ W_cat, const float* __restrict__ b_kb) {
    int idx = blockIdx.x * 256 + threadIdx.x;          // over B*H*H
    int h = idx & 511;
    int g = (idx >> 9) & 511;
    int b = idx >> 18;
    float w = fmaf(W_cat[g * (2 * H_DIM) + h], g_projmem[b * H_DIM + h],
                   W_cat[g * (2 * H_DIM) + H_DIM + h]);
    __half hi, lo;
    split2(w, hi, lo);
    g_Wchi[idx] = hi;
    g_Wclo[idx] = lo;
    float s = warp_sum(b_kb[h] * w);
    if ((threadIdx.x & 31) == 0) atomicAdd(&g_cb[(b << 9) + g], s);
}

// ---------------- transpose+split W_kb [h][kk] -> W_kbT [kk][h] hi/lo ----------------
__global__ void k_split_wkbT(const float* __restrict__ W_kb) {
    __shared__ float t[32][33];
    int kk0 = blockIdx.x * 32, h0 = blockIdx.y * 32;
    int tx = threadIdx.x & 31, ty = threadIdx.x >> 5;
    #pragma unroll
    for (int i = 0; i < 4; i++) {
        int h = ty + i * 8;
        t[h][tx] = W_kb[(size_t)(h0 + h) * KB_DIM + kk0 + tx];
    }
    __syncthreads();
    #pragma unroll
    for (int i = 0; i < 4; i++) {
        int kk = ty + i * 8;
        float v = t[tx][kk];
        __half h, l;
        split2(v, h, l);
        size_t o = (size_t)(kk0 + kk) * H_DIM + h0 + tx;
        g_WkbThi[o] = h;
        g_WkbTlo[o] = l;
    }
}

// ---------------- weight split W_cat2 ----------------
__global__ void k_split_w2(const float* __restrict__ src) {
    int i = blockIdx.x * 256 + threadIdx.x;            // over H*H
    __half h, l;
    split2(src[i], h, l);
    g_W2hi[i] = h;
    g_W2lo[i] = l;
}

// ---------------- HMMA GEMM: CTA 128x64, BK=16, double-buffered cp.async + ldmatrix ------
// (R12-proven hot loop; fp16 hi/lo)
// MODE 4: A=g_Wc[b],  B=g_WkbT,  3-pass, no bias -> split g_M[b]
// MODE 2: A=g_A[b],   B=g_M[b],  2-pass, +g_cb, ELU -> split g_H2[b]
// MODE 3: A=g_H2[b],  B=g_W2,    2-pass, +b_cat2 -> fused elu(h2*ctl)*W_attn -> atomic logits
// Stage: Ah[128][48B] @0, Al @6144, Bh[64][48B] @12288, Bl @15360.  18432 B/stage.
#define STAGE_BYTES 18432

template <int MODE>
__global__ __launch_bounds__(256, 2)
void kg(const float* __restrict__ bias_ext, const float* __restrict__ control,
        const float* __restrict__ W_attn) {
    __shared__ __align__(16) char smem[2 * STAGE_BYTES];
    const uint32_t sb = smem_to_u32(smem);
    const int tid = threadIdx.x, lane = tid & 31, wid = tid >> 5;
    const int m0 = blockIdx.x * 128, n0 = blockIdx.y * 64, b = blockIdx.z;

    const __half *Ahi, *Alo, *Bhi, *Blo;
    if (MODE == 4) {
        Ahi = g_Wchi + (size_t)b * H_DIM * H_DIM;  Alo = g_Wclo + (size_t)b * H_DIM * H_DIM;
        Bhi = g_WkbThi;  Blo = g_WkbTlo;
    } else if (MODE == 2) {
        Ahi = g_Ahi + (size_t)b * N_DIM * KB_DIM;  Alo = g_Alo + (size_t)b * N_DIM * KB_DIM;
        Bhi = g_Mhi + (size_t)b * H_DIM * KB_DIM;  Blo = g_Mlo + (size_t)b * H_DIM * KB_DIM;
    } else {
        Ahi = g_H2hi + (size_t)b * N_DIM * H_DIM;  Alo = g_H2lo + (size_t)b * N_DIM * H_DIM;
        Bhi = g_W2hi;  Blo = g_W2lo;
    }

    auto issue = [&](int s) {
        const uint32_t base = sb + (uint32_t)(s & 1) * STAGE_BYTES;
        const int kk0 = s * 16;
        {
            int r = tid >> 1, c = tid & 1;               // A: 128 rows x 2 chunks
            uint32_t d = base + r * 48 + c * 16;
            size_t go = (size_t)(m0 + r) * 512 + kk0 + c * 8;
            CP_ASYNC(d, Ahi + go);
            CP_ASYNC(d + 6144, Alo + go);
        }
        if (tid < 128) {
            int r = tid >> 1, c = tid & 1;               // B: 64 rows x 2 chunks
            uint32_t d = base + 12288 + r * 48 + c * 16;
            size_t go = (size_t)(n0 + r) * 512 + kk0 + c * 8;
            CP_ASYNC(d, Bhi + go);
            CP_ASYNC(d + 3072, Blo + go);
        }
        CP_COMMIT();
    };

    float acc[2][4][4] = {};
    const int mb = (wid & 3) * 32;       // 4 warps in m
    const int nb = (wid >> 2) * 32;      // 2 warps in n

    issue(0);
    for (int s = 0; s < 32; s++) {
        if (s < 31) { issue(s + 1); CP_WAIT(1); }
        else        { CP_WAIT(0); }
        __syncthreads();
        const uint32_t cb = sb + (uint32_t)(s & 1) * STAGE_BYTES;
        const uint32_t aAddr = cb + (mb + (lane & 15)) * 48 + ((lane >> 4) << 4);
        const uint32_t bAddr = cb + 12288 +
            (nb + ((lane >> 4) << 3) + (lane & 7)) * 48 + (((lane >> 3) & 1) << 4);
        uint32_t ah[2][4], bh[2][4], bl[2][4];
        ldsm4(ah[0], aAddr);
        ldsm4(ah[1], aAddr + 16 * 48);
        ldsm4(bh[0], bAddr);
        ldsm4(bh[1], bAddr + 16 * 48);
        ldsm4(bl[0], bAddr + 3072);
        ldsm4(bl[1], bAddr + 3072 + 16 * 48);
        if (MODE == 4) {
            uint32_t al[2][4];
            ldsm4(al[0], aAddr + 6144);
            ldsm4(al[1], aAddr + 6144 + 16 * 48);
            #pragma unroll
            for (int mf = 0; mf < 2; mf++) {
                #pragma unroll
                for (int nf = 0; nf < 4; nf++) {
                    const uint32_t* BH = &bh[nf >> 1][(nf & 1) * 2];
                    const uint32_t* BL = &bl[nf >> 1][(nf & 1) * 2];
                    mma_f16(acc[mf][nf], ah[mf], BH);
                    mma_f16(acc[mf][nf], ah[mf], BL);
                    mma_f16(acc[mf][nf], al[mf], BH);
                }
            }
        } else {
            #pragma unroll
            for (int mf = 0; mf < 2; mf++) {
                #pragma unroll
                for (int nf = 0; nf < 4; nf++) {
                    const uint32_t* BH = &bh[nf >> 1][(nf & 1) * 2];
                    const uint32_t* BL = &bl[nf >> 1][(nf & 1) * 2];
                    mma_f16(acc[mf][nf], ah[mf], BH);
                    mma_f16(acc[mf][nf], ah[mf], BL);
                }
            }
        }
        __syncthreads();
    }

    const int gr = lane >> 2, gc = (lane & 3) * 2;

    if (MODE == 3) {
        // fused: logits[b,row] += sum_col elu((acc+bias)*ctl[col]) * W_attn[col]
        const float* ctl = control + ((T_DIM - 1) * B_DIM + b) * H_DIM;
        float part[2][2] = {};
        #pragma unroll
        for (int nf = 0; nf < 4; nf++) {
            int col = n0 + nb + nf * 8 + gc;
            float bv0 = __ldg(bias_ext + col), bv1 = __ldg(bias_ext + col + 1);
            float c0 = __ldg(ctl + col), c1 = __ldg(ctl + col + 1);
            float w0 = __ldg(W_attn + col), w1 = __ldg(W_attn + col + 1);
            #pragma unroll
            for (int mf = 0; mf < 2; mf++) {
                #pragma unroll
                for (int h = 0; h < 2; h++) {
                    float x0 = (acc[mf][nf][h * 2 + 0] + bv0) * c0;
                    float x1 = (acc[mf][nf][h * 2 + 1] + bv1) * c1;
                    x0 = (x0 > 0.f) ? x0 : expm1f(x0);
                    x1 = (x1 > 0.f) ? x1 : expm1f(x1);
                    part[mf][h] = fmaf(x0, w0, part[mf][h]);
                    part[mf][h] = fmaf(x1, w1, part[mf][h]);
                }
            }
        }
        #pragma unroll
        for (int mf = 0; mf < 2; mf++) {
            #pragma unroll
            for (int h = 0; h < 2; h++) {
                float r = part[mf][h];
                r += __shfl_xor_sync(0xffffffffu, r, 1);
                r += __shfl_xor_sync(0xffffffffu, r, 2);
                if ((lane & 3) == 0) {
                    int row = m0 + mb + mf * 16 + gr + h * 8;
                    atomicAdd(&g_logits[b * N_DIM + row], r);
                }
            }
        }
        return;
    }

    const float* bias = g_cb + b * H_DIM;
    #pragma unroll
    for (int mf = 0; mf < 2; mf++) {
        #pragma unroll
        for (int nf = 0; nf < 4; nf++) {
            int col = n0 + nb + nf * 8 + gc;
            float bv0 = 0.f, bv1 = 0.f;
            if (MODE == 2) { bv0 = __ldg(bias + col); bv1 = __ldg(bias + col + 1); }
            #pragma unroll
            for (int h = 0; h < 2; h++) {
                int row = m0 + mb + mf * 16 + gr + h * 8;
                float v0 = acc[mf][nf][h * 2 + 0] + bv0;
                float v1 = acc[mf][nf][h * 2 + 1] + bv1;
                if (MODE == 2) {
                    v0 = (v0 > 0.f) ? v0 : expm1f(v0);
                    v1 = (v1 > 0.f) ? v1 : expm1f(v1);
                }
                size_t o = ((size_t)b * ((MODE == 4) ? H_DIM : N_DIM) + row) * 512 + col;
                __half h0, l0, h1, l1;
                split2(v0, h0, l0);
                split2(v1, h1, l1);
                __half2 hv; hv.x = h0; hv.y = h1;
                __half2 lv; lv.x = l0; lv.y = l1;
                if (MODE == 4) {
                    *(__half2*)(g_Mhi + o) = hv;
                    *(__half2*)(g_Mlo + o) = lv;
                } else {
                    *(__half2*)(g_H2hi + o) = hv;
                    *(__half2*)(g_H2lo + o) = lv;
                }
            }
        }
    }
}

// ---------------- softmax / read ----------------
__global__ void k_softmax() {
    int b = blockIdx.x;
    int t = threadIdx.x;
    __shared__ float red[256];
    float m = -1e30f;
    for (int i = t; i < N_DIM; i += 256) m = fmaxf(m, g_logits[b * N_DIM + i]);
    red[t] = m;
    __syncthreads();
    for (int s = 128; s > 0; s >>= 1) {
        if (t < s) red[t] = fmaxf(red[t], red[t + s]);
        __syncthreads();
    }
    m = red[0];
    __syncthreads();
    float sum = 0.f;
    for (int i = t; i < N_DIM; i += 256) {
        float e = expf(g_logits[b * N_DIM + i] - m);
        g_a[b * N_DIM + i] = e;
        sum += e;
    }
    red[t] = sum;
    __syncthreads();
    for (int s = 128; s > 0; s >>= 1) {
        if (t < s) red[t] += red[t + s];
        __syncthreads();
    }
    float inv = 1.f / red[0];
    for (int i = t; i < N_DIM; i += 256) g_a[b * N_DIM + i] *= inv;
}

__global__ void k_read(const float* __restrict__ know, float* __restrict__ out) {
    int b = blockIdx.y;
    __shared__ __align__(16) float a_sh[N_DIM];
    for (int i = threadIdx.x; i < N_DIM; i += 256) a_sh[i] = g_a[b * N_DIM + i];
    __syncthreads();
    int warp = threadIdx.x >> 5, lane = threadIdx.x & 31;
    int kk = blockIdx.x * 8 + warp;
    const float* kr = know + ((size_t)b * KB_DIM + kk) * N_DIM;
    float s = 0.f;
    #pragma unroll
    for (int it = 0; it < 16; it++) {
        int n = it * 128 + lane * 4;
        float4 v = *(const float4*)(kr + n);
        float4 a = *(const float4*)&a_sh[n];
        s = fmaf(v.x, a.x, s);
        s = fmaf(v.y, a.y, s);
        s = fmaf(v.z, a.z, s);
        s = fmaf(v.w, a.w, s);
    }
    s = warp_sum(s);
    if (lane == 0) out[b * KB_DIM + kk] = s;
}

// ---------------- launch ----------------
extern "C" void kernel_launch(void* const* d_in, const int* in_sizes, int n_in,
                              void* d_out, int out_size) {
    const float* memory  = (const float*)d_in[0];
    const float* know    = (const float*)d_in[1];
    const float* control = (const float*)d_in[2];
    const float* masks   = (const float*)d_in[3];
    const float* W_mem   = (const float*)d_in[4];
    const float* b_mem   = (const float*)d_in[5];
    const float* W_kb    = (const float*)d_in[6];
    const float* b_kb    = (const float*)d_in[7];
    const float* W_cat   = (const float*)d_in[8];
    const float* b_cat   = (const float*)d_in[9];
    const float* W_cat2  = (const float*)d_in[10];
    const float* b_cat2  = (const float*)d_in[11];
    const float* W_attn  = (const float*)d_in[12];
    float* out = (float*)d_out;

    k_convT<<<dim3(N_DIM / 32, KB_DIM / 32, B_DIM), 256>>>(know);
    k_projmem<<<B_DIM, 512>>>(memory, masks, W_mem, b_mem, b_cat);
    k_wc_split<<<(B_DIM * H_DIM * H_DIM) / 256, 256>>>(W_cat, b_kb);
    k_split_wkbT<<<dim3(KB_DIM / 32, H_DIM / 32), 256>>>(W_kb);
    k_split_w2<<<(H_DIM * H_DIM) / 256, 256>>>(W_cat2);

    // weight fold: M_b = Wc_b @ W_kb   (512x512, K=512, per batch; 3-pass)
    kg<4><<<dim3(H_DIM / 128, H_DIM / 64, B_DIM), 256>>>(nullptr, nullptr, nullptr);
    // h = elu(k @ M_b^T + c_b)   (2-pass)
    kg<2><<<dim3(N_DIM / 128, H_DIM / 64, B_DIM), 256>>>(nullptr, nullptr, nullptr);
    // logits += sum_g elu((h @ W2^T + b_cat2) * ctl) * W_attn   (2-pass, fused)
    kg<3><<<dim3(N_DIM / 128, H_DIM / 64, B_DIM), 256>>>(b_cat2, control, W_attn);

    k_softmax<<<B_DIM, 256>>>();
    k_read<<<dim3(KB_DIM / 8, B_DIM), 256>>>(know, out);
}

// round 16
// speedup vs baseline: 1.3406x; 1.1840x over previous
#include <cuda_runtime.h>
#include <cuda_fp16.h>
#include <math.h>
#include <cstdint>

#define T_DIM 4
#define B_DIM 32
#define N_DIM 2048
#define H_DIM 512
#define KB_DIM 512

// ---------------- device scratch (no allocations) ----------------
__device__ __align__(16) float g_projmem[B_DIM * H_DIM];
__device__ __align__(16) float g_logits[B_DIM * N_DIM];
__device__ __align__(16) float g_a[B_DIM * N_DIM];
__device__ __align__(16) float g_cb[B_DIM * H_DIM];      // folded bias per batch

__device__ __align__(16) __half g_Ahi[(size_t)B_DIM * N_DIM * KB_DIM];
__device__ __align__(16) __half g_H2hi[(size_t)B_DIM * N_DIM * H_DIM];
__device__ __align__(16) __half g_WkbThi[KB_DIM * H_DIM];   // W_kb^T [kk][h]
__device__ __align__(16) __half g_WkbTlo[KB_DIM * H_DIM];
__device__ __align__(16) __half g_W2hi[H_DIM * H_DIM];
__device__ __align__(16) __half g_W2lo[H_DIM * H_DIM];
__device__ __align__(16) __half g_Wchi[(size_t)B_DIM * H_DIM * H_DIM];
__device__ __align__(16) __half g_Wclo[(size_t)B_DIM * H_DIM * H_DIM];
__device__ __align__(16) __half g_Mhi[(size_t)B_DIM * H_DIM * KB_DIM];  // folded weight
__device__ __align__(16) __half g_Mlo[(size_t)B_DIM * H_DIM * KB_DIM];

// ---------------- helpers (baseline ISA only) ----------------
__device__ __forceinline__ uint32_t smem_to_u32(const void* p) {
    uint32_t a;
    asm("{ .reg .u64 t; cvta.to.shared.u64 t, %1; cvt.u32.u64 %0, t; }" : "=r"(a) : "l"(p));
    return a;
}
#define CP_ASYNC(dst, src) \
    asm volatile("cp.async.cg.shared.global [%0], [%1], 16;" :: "r"(dst), "l"(src) : "memory")
#define CP_COMMIT() asm volatile("cp.async.commit_group;" ::: "memory")
#define CP_WAIT(n)  asm volatile("cp.async.wait_group %0;" :: "n"(n) : "memory")

__device__ __forceinline__ void ldsm4(uint32_t* r, uint32_t addr) {
    asm volatile("ldmatrix.sync.aligned.m8n8.x4.shared.b16 {%0,%1,%2,%3}, [%4];"
                 : "=r"(r[0]), "=r"(r[1]), "=r"(r[2]), "=r"(r[3]) : "r"(addr));
}
__device__ __forceinline__ void mma_f16(float* c, const uint32_t* a, const uint32_t* b) {
    asm volatile(
        "mma.sync.aligned.m16n8k16.row.col.f32.f16.f16.f32 "
        "{%0,%1,%2,%3}, {%4,%5,%6,%7}, {%8,%9}, {%0,%1,%2,%3};"
        : "+f"(c[0]), "+f"(c[1]), "+f"(c[2]), "+f"(c[3])
        : "r"(a[0]), "r"(a[1]), "r"(a[2]), "r"(a[3]), "r"(b[0]), "r"(b[1]));
}
__device__ __forceinline__ void split2(float x, __half& h, __half& l) {
    h = __float2half(x);
    l = __float2half(x - __half2float(h));
}
__device__ __forceinline__ float warp_sum(float v) {
    #pragma unroll
    for (int o = 16; o > 0; o >>= 1) v += __shfl_xor_sync(0xffffffffu, v, o);
    return v;
}

// ---------------- K0: proj_mem; also init g_cb=b_cat and zero g_logits ----------------
__global__ void k_projmem(const float* __restrict__ memory, const float* __restrict__ masks,
                          const float* __restrict__ W_mem, const float* __restrict__ b_mem,
                          const float* __restrict__ b_cat) {
    int b = blockIdx.x;
    int t = threadIdx.x;
    g_cb[b * H_DIM + t] = b_cat[t];
    #pragma unroll
    for (int i = 0; i < 4; i++) g_logits[b * N_DIM + t * 4 + i] = 0.f;
    __shared__ float lm[H_DIM];
    lm[t] = memory[((T_DIM - 1) * B_DIM + b) * H_DIM + t] * masks[b * H_DIM + t];
    __syncthreads();
    const float* w = W_mem + t * H_DIM;
    float s = 0.f;
    #pragma unroll 8
    for (int j = 0; j < H_DIM; j++) s = fmaf(lm[j], w[j], s);
    g_projmem[b * H_DIM + t] = s + b_mem[t];
}

// ---------------- K1: folded Wc -> fp16 hi/lo; also accumulate cb += b_kb.Wc ----------
__global__ void k_wc_split(const float* __restrict__ W_cat, const float* __restrict__ b_kb) {
    int idx = blockIdx.x * 256 + threadIdx.x;          // over B*H*H
    int h = idx & 511;
    int g = (idx >> 9) & 511;
    int b = idx >> 18;
    float w = fmaf(W_cat[g * (2 * H_DIM) + h], g_projmem[b * H_DIM + h],
                   W_cat[g * (2 * H_DIM) + H_DIM + h]);
    __half hi, lo;
    split2(w, hi, lo);
    g_Wchi[idx] = hi;
    g_Wclo[idx] = lo;
    float s = warp_sum(b_kb[h] * w);
    if ((threadIdx.x & 31) == 0) atomicAdd(&g_cb[(b << 9) + g], s);
}

// ---------------- transpose+split W_kb [h][kk] -> W_kbT [kk][h] hi/lo ----------------
__global__ void k_split_wkbT(const float* __restrict__ W_kb) {
    __shared__ float t[32][33];
    int kk0 = blockIdx.x * 32, h0 = blockIdx.y * 32;
    int tx = threadIdx.x & 31, ty = threadIdx.x >> 5;
    #pragma unroll
    for (int i = 0; i < 4; i++) {
        int h = ty + i * 8;
        t[h][tx] = W_kb[(size_t)(h0 + h) * KB_DIM + kk0 + tx];
    }
    __syncthreads();
    #pragma unroll
    for (int i = 0; i < 4; i++) {
        int kk = ty + i * 8;
        float v = t[tx][kk];
        __half h, l;
        split2(v, h, l);
        size_t o = (size_t)(kk0 + kk) * H_DIM + h0 + tx;
        g_WkbThi[o] = h;
        g_WkbTlo[o] = l;
    }
}

// ---------------- transpose know[b][kk][n] -> A[b][n][kk] fp16 (hi only) --------------
__global__ void k_convT(const float* __restrict__ know) {
    __shared__ float t[32][33];
    int b = blockIdx.z;
    int n0 = blockIdx.x * 32, k0 = blockIdx.y * 32;
    int tx = threadIdx.x & 31, ty = threadIdx.x >> 5;
    const float* src = know + ((size_t)b * KB_DIM + k0) * (size_t)N_DIM + n0;
    #pragma unroll
    for (int i = 0; i < 4; i++) {
        int kk = ty + i * 8;
        t[kk][tx] = src[(size_t)kk * N_DIM + tx];
    }
    __syncthreads();
    #pragma unroll
    for (int i = 0; i < 4; i++) {
        int n = ty + i * 8;
        size_t o = ((size_t)b * N_DIM + n0 + n) * KB_DIM + k0 + tx;
        g_Ahi[o] = __float2half(t[tx][n]);
    }
}

// ---------------- weight split W_cat2 ----------------
__global__ void k_split_w2(const float* __restrict__ src) {
    int i = blockIdx.x * 256 + threadIdx.x;            // over H*H
    __half h, l;
    split2(src[i], h, l);
    g_W2hi[i] = h;
    g_W2lo[i] = l;
}

// ---------------- HMMA GEMM: CTA 128x64, BK=16, double-buffered cp.async + ldmatrix ------
// (R12-proven hot loop; fp16 hi/lo)
// MODE 4: A=g_Wc[b] hi/lo, B=g_WkbT, 3-pass, no bias -> split g_M[b]
// MODE 2: A=g_Ahi[b],      B=g_M[b], 2-pass, +g_cb, ELU -> g_H2hi[b]
// MODE 3: A=g_H2hi[b],     B=g_W2,   2-pass, +b_cat2 -> fused elu(h2*ctl)*W_attn -> logits
// Stage: Ah[128][48B] @0, Al @6144 (MODE4 only), Bh[64][48B] @12288, Bl @15360.
#define STAGE_BYTES 18432

template <int MODE>
__global__ __launch_bounds__(256, 2)
void kg(const float* __restrict__ bias_ext, const float* __restrict__ control,
        const float* __restrict__ W_attn) {
    __shared__ __align__(16) char smem[2 * STAGE_BYTES];
    const uint32_t sb = smem_to_u32(smem);
    const int tid = threadIdx.x, lane = tid & 31, wid = tid >> 5;
    const int m0 = blockIdx.x * 128, n0 = blockIdx.y * 64, b = blockIdx.z;

    const __half *Ahi, *Alo = nullptr, *Bhi, *Blo;
    if (MODE == 4) {
        Ahi = g_Wchi + (size_t)b * H_DIM * H_DIM;  Alo = g_Wclo + (size_t)b * H_DIM * H_DIM;
        Bhi = g_WkbThi;  Blo = g_WkbTlo;
    } else if (MODE == 2) {
        Ahi = g_Ahi + (size_t)b * N_DIM * KB_DIM;
        Bhi = g_Mhi + (size_t)b * H_DIM * KB_DIM;  Blo = g_Mlo + (size_t)b * H_DIM * KB_DIM;
    } else {
        Ahi = g_H2hi + (size_t)b * N_DIM * H_DIM;
        Bhi = g_W2hi;  Blo = g_W2lo;
    }

    auto issue = [&](int s) {
        const uint32_t base = sb + (uint32_t)(s & 1) * STAGE_BYTES;
        const int kk0 = s * 16;
        {
            int r = tid >> 1, c = tid & 1;               // A: 128 rows x 2 chunks
            uint32_t d = base + r * 48 + c * 16;
            size_t go = (size_t)(m0 + r) * 512 + kk0 + c * 8;
            CP_ASYNC(d, Ahi + go);
            if (MODE == 4) CP_ASYNC(d + 6144, Alo + go);
        }
        if (tid < 128) {
            int r = tid >> 1, c = tid & 1;               // B: 64 rows x 2 chunks
            uint32_t d = base + 12288 + r * 48 + c * 16;
            size_t go = (size_t)(n0 + r) * 512 + kk0 + c * 8;
            CP_ASYNC(d, Bhi + go);
            CP_ASYNC(d + 3072, Blo + go);
        }
        CP_COMMIT();
    };

    float acc[2][4][4] = {};
    const int mb = (wid & 3) * 32;       // 4 warps in m
    const int nb = (wid >> 2) * 32;      // 2 warps in n

    issue(0);
    for (int s = 0; s < 32; s++) {
        if (s < 31) { issue(s + 1); CP_WAIT(1); }
        else        { CP_WAIT(0); }
        __syncthreads();
        const uint32_t cb = sb + (uint32_t)(s & 1) * STAGE_BYTES;
        const uint32_t aAddr = cb + (mb + (lane & 15)) * 48 + ((lane >> 4) << 4);
        const uint32_t bAddr = cb + 12288 +
            (nb + ((lane >> 4) << 3) + (lane & 7)) * 48 + (((lane >> 3) & 1) << 4);
        uint32_t ah[2][4], bh[2][4], bl[2][4];
        ldsm4(ah[0], aAddr);
        ldsm4(ah[1], aAddr + 16 * 48);
        ldsm4(bh[0], bAddr);
        ldsm4(bh[1], bAddr + 16 * 48);
        ldsm4(bl[0], bAddr + 3072);
        ldsm4(bl[1], bAddr + 3072 + 16 * 48);
        if (MODE == 4) {
            uint32_t al[2][4];
            ldsm4(al[0], aAddr + 6144);
            ldsm4(al[1], aAddr + 6144 + 16 * 48);
            #pragma unroll
            for (int mf = 0; mf < 2; mf++) {
                #pragma unroll
                for (int nf = 0; nf < 4; nf++) {
                    const uint32_t* BH = &bh[nf >> 1][(nf & 1) * 2];
                    const uint32_t* BL = &bl[nf >> 1][(nf & 1) * 2];
                    mma_f16(acc[mf][nf], ah[mf], BH);
                    mma_f16(acc[mf][nf], ah[mf], BL);
                    mma_f16(acc[mf][nf], al[mf], BH);
                }
            }
        } else {
            #pragma unroll
            for (int mf = 0; mf < 2; mf++) {
                #pragma unroll
                for (int nf = 0; nf < 4; nf++) {
                    const uint32_t* BH = &bh[nf >> 1][(nf & 1) * 2];
                    const uint32_t* BL = &bl[nf >> 1][(nf & 1) * 2];
                    mma_f16(acc[mf][nf], ah[mf], BH);
                    mma_f16(acc[mf][nf], ah[mf], BL);
                }
            }
        }
        __syncthreads();
    }

    const int gr = lane >> 2, gc = (lane & 3) * 2;

    if (MODE == 3) {
        // fused: logits[b,row] += sum_col elu((acc+bias)*ctl[col]) * W_attn[col]
        const float* ctl = control + ((T_DIM - 1) * B_DIM + b) * H_DIM;
        float part[2][2] = {};
        #pragma unroll
        for (int nf = 0; nf < 4; nf++) {
            int col = n0 + nb + nf * 8 + gc;
            float bv0 = __ldg(bias_ext + col), bv1 = __ldg(bias_ext + col + 1);
            float c0 = __ldg(ctl + col), c1 = __ldg(ctl + col + 1);
            float w0 = __ldg(W_attn + col), w1 = __ldg(W_attn + col + 1);
            #pragma unroll
            for (int mf = 0; mf < 2; mf++) {
                #pragma unroll
                for (int h = 0; h < 2; h++) {
                    float x0 = (acc[mf][nf][h * 2 + 0] + bv0) * c0;
                    float x1 = (acc[mf][nf][h * 2 + 1] + bv1) * c1;
                    x0 = (x0 > 0.f) ? x0 : expm1f(x0);
                    x1 = (x1 > 0.f) ? x1 : expm1f(x1);
                    part[mf][h] = fmaf(x0, w0, part[mf][h]);
                    part[mf][h] = fmaf(x1, w1, part[mf][h]);
                }
            }
        }
        #pragma unroll
        for (int mf = 0; mf < 2; mf++) {
            #pragma unroll
            for (int h = 0; h < 2; h++) {
                float r = part[mf][h];
                r += __shfl_xor_sync(0xffffffffu, r, 1);
                r += __shfl_xor_sync(0xffffffffu, r, 2);
                if ((lane & 3) == 0) {
                    int row = m0 + mb + mf * 16 + gr + h * 8;
                    atomicAdd(&g_logits[b * N_DIM + row], r);
                }
            }
        }
        return;
    }

    const float* bias = g_cb + b * H_DIM;
    #pragma unroll
    for (int mf = 0; mf < 2; mf++) {
        #pragma unroll
        for (int nf = 0; nf < 4; nf++) {
            int col = n0 + nb + nf * 8 + gc;
            float bv0 = 0.f, bv1 = 0.f;
            if (MODE == 2) { bv0 = __ldg(bias + col); bv1 = __ldg(bias + col + 1); }
            #pragma unroll
            for (int h = 0; h < 2; h++) {
                int row = m0 + mb + mf * 16 + gr + h * 8;
                float v0 = acc[mf][nf][h * 2 + 0] + bv0;
                float v1 = acc[mf][nf][h * 2 + 1] + bv1;
                if (MODE == 2) {
                    v0 = (v0 > 0.f) ? v0 : expm1f(v0);
                    v1 = (v1 > 0.f) ? v1 : expm1f(v1);
                    size_t o = ((size_t)b * N_DIM + row) * 512 + col;
                    __half2 hv; hv.x = __float2half(v0); hv.y = __float2half(v1);
                    *(__half2*)(g_H2hi + o) = hv;
                } else {
                    size_t o = ((size_t)b * H_DIM + row) * 512 + col;
                    __half h0, l0, h1, l1;
                    split2(v0, h0, l0);
                    split2(v1, h1, l1);
                    __half2 hv; hv.x = h0; hv.y = h1;
                    __half2 lv; lv.x = l0; lv.y = l1;
                    *(__half2*)(g_Mhi + o) = hv;
                    *(__half2*)(g_Mlo + o) = lv;
                }
            }
        }
    }
}

// ---------------- softmax / read ----------------
__global__ void k_softmax() {
    int b = blockIdx.x;
    int t = threadIdx.x;
    __shared__ float red[256];
    float m = -1e30f;
    for (int i = t; i < N_DIM; i += 256) m = fmaxf(m, g_logits[b * N_DIM + i]);
    red[t] = m;
    __syncthreads();
    for (int s = 128; s > 0; s >>= 1) {
        if (t < s) red[t] = fmaxf(red[t], red[t + s]);
        __syncthreads();
    }
    m = red[0];
    __syncthreads();
    float sum = 0.f;
    for (int i = t; i < N_DIM; i += 256) {
        float e = expf(g_logits[b * N_DIM + i] - m);
        g_a[b * N_DIM + i] = e;
        sum += e;
    }
    red[t] = sum;
    __syncthreads();
    for (int s = 128; s > 0; s >>= 1) {
        if (t < s) red[t] += red[t + s];
        __syncthreads();
    }
    float inv = 1.f / red[0];
    for (int i = t; i < N_DIM; i += 256) g_a[b * N_DIM + i] *= inv;
}

__global__ void k_read(const float* __restrict__ know, float* __restrict__ out) {
    int b = blockIdx.y;
    __shared__ __align__(16) float a_sh[N_DIM];
    for (int i = threadIdx.x; i < N_DIM; i += 256) a_sh[i] = g_a[b * N_DIM + i];
    __syncthreads();
    int warp = threadIdx.x >> 5, lane = threadIdx.x & 31;
    int kk = blockIdx.x * 8 + warp;
    const float* kr = know + ((size_t)b * KB_DIM + kk) * N_DIM;
    float s = 0.f;
    #pragma unroll
    for (int it = 0; it < 16; it++) {
        int n = it * 128 + lane * 4;
        float4 v = *(const float4*)(kr + n);
        float4 a = *(const float4*)&a_sh[n];
        s = fmaf(v.x, a.x, s);
        s = fmaf(v.y, a.y, s);
        s = fmaf(v.z, a.z, s);
        s = fmaf(v.w, a.w, s);
    }
    s = warp_sum(s);
    if (lane == 0) out[b * KB_DIM + kk] = s;
}

// ---------------- launch (kg<4> at position 4: ncu captures the 4th launch) ------------
extern "C" void kernel_launch(void* const* d_in, const int* in_sizes, int n_in,
                              void* d_out, int out_size) {
    const float* memory  = (const float*)d_in[0];
    const float* know    = (const float*)d_in[1];
    const float* control = (const float*)d_in[2];
    const float* masks   = (const float*)d_in[3];
    const float* W_mem   = (const float*)d_in[4];
    const float* b_mem   = (const float*)d_in[5];
    const float* W_kb    = (const float*)d_in[6];
    const float* b_kb    = (const float*)d_in[7];
    const float* W_cat   = (const float*)d_in[8];
    const float* b_cat   = (const float*)d_in[9];
    const float* W_cat2  = (const float*)d_in[10];
    const float* b_cat2  = (const float*)d_in[11];
    const float* W_attn  = (const float*)d_in[12];
    float* out = (float*)d_out;

    k_projmem<<<B_DIM, 512>>>(memory, masks, W_mem, b_mem, b_cat);           // 1
    k_wc_split<<<(B_DIM * H_DIM * H_DIM) / 256, 256>>>(W_cat, b_kb);         // 2
    k_split_wkbT<<<dim3(KB_DIM / 32, H_DIM / 32), 256>>>(W_kb);              // 3
    // weight fold: M_b = Wc_b @ W_kb   (512x512, K=512, per batch; 3-pass)
    kg<4><<<dim3(H_DIM / 128, H_DIM / 64, B_DIM), 256>>>(nullptr, nullptr, nullptr);  // 4 <- ncu
    k_convT<<<dim3(N_DIM / 32, KB_DIM / 32, B_DIM), 256>>>(know);            // 5
    // h = elu(k @ M_b^T + c_b)   (2-pass)
    kg<2><<<dim3(N_DIM / 128, H_DIM / 64, B_DIM), 256>>>(nullptr, nullptr, nullptr);  // 6
    k_split_w2<<<(H_DIM * H_DIM) / 256, 256>>>(W_cat2);                      // 7
    // logits += sum_g elu((h @ W2^T + b_cat2) * ctl) * W_attn   (2-pass, fused)
    kg<3><<<dim3(N_DIM / 128, H_DIM / 64, B_DIM), 256>>>(b_cat2, control, W_attn);    // 8
    k_softmax<<<B_DIM, 256>>>();                                             // 9
    k_read<<<dim3(KB_DIM / 8, B_DIM), 256>>>(know, out);                     // 10
}

// round 17
// speedup vs baseline: 1.3888x; 1.0360x over previous
#include <cuda_runtime.h>
#include <cuda_fp16.h>
#include <math.h>
#include <cstdint>

#define T_DIM 4
#define B_DIM 32
#define N_DIM 2048
#define H_DIM 512
#define KB_DIM 512

// ---------------- device scratch (no allocations) ----------------
__device__ __align__(16) float g_projmem[B_DIM * H_DIM];
__device__ __align__(16) float g_logits[B_DIM * N_DIM];
__device__ __align__(16) float g_a[B_DIM * N_DIM];
__device__ __align__(16) float g_cb[B_DIM * H_DIM];      // folded bias per batch

__device__ __align__(16) __half g_Ahi[(size_t)B_DIM * N_DIM * KB_DIM];
__device__ __align__(16) __half g_H2hi[(size_t)B_DIM * N_DIM * H_DIM];
__device__ __align__(16) __half g_WkbThi[KB_DIM * H_DIM];   // W_kb^T [kk][h]
__device__ __align__(16) __half g_WkbTlo[KB_DIM * H_DIM];
__device__ __align__(16) __half g_W2hi[H_DIM * H_DIM];
__device__ __align__(16) __half g_W2lo[H_DIM * H_DIM];
__device__ __align__(16) __half g_Wchi[(size_t)B_DIM * H_DIM * H_DIM];
__device__ __align__(16) __half g_Wclo[(size_t)B_DIM * H_DIM * H_DIM];
__device__ __align__(16) __half g_Mhi[(size_t)B_DIM * H_DIM * KB_DIM];  // folded weight
__device__ __align__(16) __half g_Mlo[(size_t)B_DIM * H_DIM * KB_DIM];

// ---------------- helpers (baseline ISA only) ----------------
__device__ __forceinline__ uint32_t smem_to_u32(const void* p) {
    uint32_t a;
    asm("{ .reg .u64 t; cvta.to.shared.u64 t, %1; cvt.u32.u64 %0, t; }" : "=r"(a) : "l"(p));
    return a;
}
#define CP_ASYNC(dst, src) \
    asm volatile("cp.async.cg.shared.global [%0], [%1], 16;" :: "r"(dst), "l"(src) : "memory")
#define CP_COMMIT() asm volatile("cp.async.commit_group;" ::: "memory")
#define CP_WAIT(n)  asm volatile("cp.async.wait_group %0;" :: "n"(n) : "memory")

__device__ __forceinline__ void ldsm4(uint32_t* r, uint32_t addr) {
    asm volatile("ldmatrix.sync.aligned.m8n8.x4.shared.b16 {%0,%1,%2,%3}, [%4];"
                 : "=r"(r[0]), "=r"(r[1]), "=r"(r[2]), "=r"(r[3]) : "r"(addr));
}
__device__ __forceinline__ void mma_f16(float* c, const uint32_t* a, const uint32_t* b) {
    asm volatile(
        "mma.sync.aligned.m16n8k16.row.col.f32.f16.f16.f32 "
        "{%0,%1,%2,%3}, {%4,%5,%6,%7}, {%8,%9}, {%0,%1,%2,%3};"
        : "+f"(c[0]), "+f"(c[1]), "+f"(c[2]), "+f"(c[3])
        : "r"(a[0]), "r"(a[1]), "r"(a[2]), "r"(a[3]), "r"(b[0]), "r"(b[1]));
}
__device__ __forceinline__ void split2(float x, __half& h, __half& l) {
    h = __float2half(x);
    l = __float2half(x - __half2float(h));
}
__device__ __forceinline__ float warp_sum(float v) {
    #pragma unroll
    for (int o = 16; o > 0; o >>= 1) v += __shfl_xor_sync(0xffffffffu, v, o);
    return v;
}

// ---------------- K0: proj_mem; also init g_cb=b_cat and zero g_logits ----------------
__global__ void k_projmem(const float* __restrict__ memory, const float* __restrict__ masks,
                          const float* __restrict__ W_mem, const float* __restrict__ b_mem,
                          const float* __restrict__ b_cat) {
    int b = blockIdx.x;
    int t = threadIdx.x;
    g_cb[b * H_DIM + t] = b_cat[t];
    #pragma unroll
    for (int i = 0; i < 4; i++) g_logits[b * N_DIM + t * 4 + i] = 0.f;
    __shared__ float lm[H_DIM];
    lm[t] = memory[((T_DIM - 1) * B_DIM + b) * H_DIM + t] * masks[b * H_DIM + t];
    __syncthreads();
    const float* w = W_mem + t * H_DIM;
    float s = 0.f;
    #pragma unroll 8
    for (int j = 0; j < H_DIM; j++) s = fmaf(lm[j], w[j], s);
    g_projmem[b * H_DIM + t] = s + b_mem[t];
}

// ---------------- K1: folded Wc -> fp16 hi/lo; also accumulate cb += b_kb.Wc ----------
__global__ void k_wc_split(const float* __restrict__ W_cat, const float* __restrict__ b_kb) {
    int idx = blockIdx.x * 256 + threadIdx.x;          // over B*H*H
    int h = idx & 511;
    int g = (idx >> 9) & 511;
    int b = idx >> 18;
    float w = fmaf(W_cat[g * (2 * H_DIM) + h], g_projmem[b * H_DIM + h],
                   W_cat[g * (2 * H_DIM) + H_DIM + h]);
    __half hi, lo;
    split2(w, hi, lo);
    g_Wchi[idx] = hi;
    g_Wclo[idx] = lo;
    float s = warp_sum(b_kb[h] * w);
    if ((threadIdx.x & 31) == 0) atomicAdd(&g_cb[(b << 9) + g], s);
}

// ---------------- transpose+split W_kb [h][kk] -> W_kbT [kk][h] hi/lo ----------------
__global__ void k_split_wkbT(const float* __restrict__ W_kb) {
    __shared__ float t[32][33];
    int kk0 = blockIdx.x * 32, h0 = blockIdx.y * 32;
    int tx = threadIdx.x & 31, ty = threadIdx.x >> 5;
    #pragma unroll
    for (int i = 0; i < 4; i++) {
        int h = ty + i * 8;
        t[h][tx] = W_kb[(size_t)(h0 + h) * KB_DIM + kk0 + tx];
    }
    __syncthreads();
    #pragma unroll
    for (int i = 0; i < 4; i++) {
        int kk = ty + i * 8;
        float v = t[tx][kk];
        __half h, l;
        split2(v, h, l);
        size_t o = (size_t)(kk0 + kk) * H_DIM + h0 + tx;
        g_WkbThi[o] = h;
        g_WkbTlo[o] = l;
    }
}

// ---------------- transpose know[b][kk][n] -> A[b][n][kk] fp16 (hi only) --------------
__global__ void k_convT(const float* __restrict__ know) {
    __shared__ float t[32][33];
    int b = blockIdx.z;
    int n0 = blockIdx.x * 32, k0 = blockIdx.y * 32;
    int tx = threadIdx.x & 31, ty = threadIdx.x >> 5;
    const float* src = know + ((size_t)b * KB_DIM + k0) * (size_t)N_DIM + n0;
    #pragma unroll
    for (int i = 0; i < 4; i++) {
        int kk = ty + i * 8;
        t[kk][tx] = src[(size_t)kk * N_DIM + tx];
    }
    __syncthreads();
    #pragma unroll
    for (int i = 0; i < 4; i++) {
        int n = ty + i * 8;
        size_t o = ((size_t)b * N_DIM + n0 + n) * KB_DIM + k0 + tx;
        g_Ahi[o] = __float2half(t[tx][n]);
    }
}

// ---------------- weight split W_cat2 ----------------
__global__ void k_split_w2(const float* __restrict__ src) {
    int i = blockIdx.x * 256 + threadIdx.x;            // over H*H
    __half h, l;
    split2(src[i], h, l);
    g_W2hi[i] = h;
    g_W2lo[i] = l;
}

// ---------------- HMMA GEMM: CTA 128x64, BK=16, cp.async pipeline + ldmatrix ------------
// MODE 4: A=g_Wc[b] hi/lo, B=g_WkbT, 3-pass, 2-stage pipe (18432 B/stage)
// MODE 2: A=g_Ahi[b],      B=g_M[b], 2-pass, 3-stage pipe (12288 B/stage), +g_cb, ELU
// MODE 3: A=g_H2hi[b],     B=g_W2,   2-pass, 3-stage pipe, fused logits epilogue
// MODE2/3 stage: A[128][48B] @0, Bh[64][48B] @6144, Bl @9216.
// MODE4   stage: A[128][48B] @0, Al @6144,  Bh @12288, Bl @15360.

template <int MODE>
__global__ __launch_bounds__(256, 2)
void kg(const float* __restrict__ bias_ext, const float* __restrict__ control,
        const float* __restrict__ W_attn) {
    constexpr int NSTAGE = (MODE == 4) ? 2 : 3;
    constexpr uint32_t SBYTES = (MODE == 4) ? 18432u : 12288u;
    constexpr uint32_t OFF_B = (MODE == 4) ? 12288u : 6144u;
    __shared__ __align__(16) char smem[36864];
    const uint32_t sb = smem_to_u32(smem);
    const int tid = threadIdx.x, lane = tid & 31, wid = tid >> 5;
    const int m0 = blockIdx.x * 128, n0 = blockIdx.y * 64, b = blockIdx.z;

    const __half *Ahi, *Alo = nullptr, *Bhi, *Blo;
    if (MODE == 4) {
        Ahi = g_Wchi + (size_t)b * H_DIM * H_DIM;  Alo = g_Wclo + (size_t)b * H_DIM * H_DIM;
        Bhi = g_WkbThi;  Blo = g_WkbTlo;
    } else if (MODE == 2) {
        Ahi = g_Ahi + (size_t)b * N_DIM * KB_DIM;
        Bhi = g_Mhi + (size_t)b * H_DIM * KB_DIM;  Blo = g_Mlo + (size_t)b * H_DIM * KB_DIM;
    } else {
        Ahi = g_H2hi + (size_t)b * N_DIM * H_DIM;
        Bhi = g_W2hi;  Blo = g_W2lo;
    }

    auto issue = [&](int s) {
        const uint32_t base = sb + (uint32_t)(s % NSTAGE) * SBYTES;
        const int kk0 = s * 16;
        {
            int r = tid >> 1, c = tid & 1;               // A: 128 rows x 2 chunks
            uint32_t d = base + r * 48 + c * 16;
            size_t go = (size_t)(m0 + r) * 512 + kk0 + c * 8;
            CP_ASYNC(d, Ahi + go);
            if (MODE == 4) CP_ASYNC(d + 6144, Alo + go);
        }
        if (tid < 128) {
            int r = tid >> 1, c = tid & 1;               // B: 64 rows x 2 chunks
            uint32_t d = base + OFF_B + r * 48 + c * 16;
            size_t go = (size_t)(n0 + r) * 512 + kk0 + c * 8;
            CP_ASYNC(d, Bhi + go);
            CP_ASYNC(d + 3072, Blo + go);
        }
        CP_COMMIT();
    };

    float acc[2][4][4] = {};
    const int mb = (wid & 3) * 32;       // 4 warps in m
    const int nb = (wid >> 2) * 32;      // 2 warps in n

    #pragma unroll
    for (int p = 0; p < NSTAGE - 1; p++) issue(p);
    for (int s = 0; s < 32; s++) {
        if (s < 32 - (NSTAGE - 1)) { issue(s + NSTAGE - 1); CP_WAIT(NSTAGE - 1); }
        else                       { CP_WAIT(0); }
        __syncthreads();
        const uint32_t cb = sb + (uint32_t)(s % NSTAGE) * SBYTES;
        const uint32_t aAddr = cb + (mb + (lane & 15)) * 48 + ((lane >> 4) << 4);
        const uint32_t bAddr = cb + OFF_B +
            (nb + ((lane >> 4) << 3) + (lane & 7)) * 48 + (((lane >> 3) & 1) << 4);
        uint32_t ah[2][4], bh[2][4], bl[2][4];
        ldsm4(ah[0], aAddr);
        ldsm4(ah[1], aAddr + 16 * 48);
        ldsm4(bh[0], bAddr);
        ldsm4(bh[1], bAddr + 16 * 48);
        ldsm4(bl[0], bAddr + 3072);
        ldsm4(bl[1], bAddr + 3072 + 16 * 48);
        if (MODE == 4) {
            uint32_t al[2][4];
            ldsm4(al[0], aAddr + 6144);
            ldsm4(al[1], aAddr + 6144 + 16 * 48);
            #pragma unroll
            for (int mf = 0; mf < 2; mf++) {
                #pragma unroll
                for (int nf = 0; nf < 4; nf++) {
                    const uint32_t* BH = &bh[nf >> 1][(nf & 1) * 2];
                    const uint32_t* BL = &bl[nf >> 1][(nf & 1) * 2];
                    mma_f16(acc[mf][nf], ah[mf], BH);
                    mma_f16(acc[mf][nf], ah[mf], BL);
                    mma_f16(acc[mf][nf], al[mf], BH);
                }
            }
        } else {
            #pragma unroll
            for (int mf = 0; mf < 2; mf++) {
                #pragma unroll
                for (int nf = 0; nf < 4; nf++) {
                    const uint32_t* BH = &bh[nf >> 1][(nf & 1) * 2];
                    const uint32_t* BL = &bl[nf >> 1][(nf & 1) * 2];
                    mma_f16(acc[mf][nf], ah[mf], BH);
                    mma_f16(acc[mf][nf], ah[mf], BL);
                }
            }
        }
        __syncthreads();
    }

    const int gr = lane >> 2, gc = (lane & 3) * 2;

    if (MODE == 3) {
        // fused: logits[b,row] += sum_col elu((acc+bias)*ctl[col]) * W_attn[col]
        const float* ctl = control + ((T_DIM - 1) * B_DIM + b) * H_DIM;
        float part[2][2] = {};
        #pragma unroll
        for (int nf = 0; nf < 4; nf++) {
            int col = n0 + nb + nf * 8 + gc;
            float bv0 = __ldg(bias_ext + col), bv1 = __ldg(bias_ext + col + 1);
            float c0 = __ldg(ctl + col), c1 = __ldg(ctl + col + 1);
            float w0 = __ldg(W_attn + col), w1 = __ldg(W_attn + col + 1);
            #pragma unroll
            for (int mf = 0; mf < 2; mf++) {
                #pragma unroll
                for (int h = 0; h < 2; h++) {
                    float x0 = (acc[mf][nf][h * 2 + 0] + bv0) * c0;
                    float x1 = (acc[mf][nf][h * 2 + 1] + bv1) * c1;
                    x0 = (x0 > 0.f) ? x0 : expm1f(x0);
                    x1 = (x1 > 0.f) ? x1 : expm1f(x1);
                    part[mf][h] = fmaf(x0, w0, part[mf][h]);
                    part[mf][h] = fmaf(x1, w1, part[mf][h]);
                }
            }
        }
        #pragma unroll
        for (int mf = 0; mf < 2; mf++) {
            #pragma unroll
            for (int h = 0; h < 2; h++) {
                float r = part[mf][h];
                r += __shfl_xor_sync(0xffffffffu, r, 1);
                r += __shfl_xor_sync(0xffffffffu, r, 2);
                if ((lane & 3) == 0) {
                    int row = m0 + mb + mf * 16 + gr + h * 8;
                    atomicAdd(&g_logits[b * N_DIM + row], r);
                }
            }
        }
        return;
    }

    const float* bias = g_cb + b * H_DIM;
    #pragma unroll
    for (int mf = 0; mf < 2; mf++) {
        #pragma unroll
        for (int nf = 0; nf < 4; nf++) {
            int col = n0 + nb + nf * 8 + gc;
            float bv0 = 0.f, bv1 = 0.f;
            if (MODE == 2) { bv0 = __ldg(bias + col); bv1 = __ldg(bias + col + 1); }
            #pragma unroll
            for (int h = 0; h < 2; h++) {
                int row = m0 + mb + mf * 16 + gr + h * 8;
                float v0 = acc[mf][nf][h * 2 + 0] + bv0;
                float v1 = acc[mf][nf][h * 2 + 1] + bv1;
                if (MODE == 2) {
                    v0 = (v0 > 0.f) ? v0 : expm1f(v0);
                    v1 = (v1 > 0.f) ? v1 : expm1f(v1);
                    size_t o = ((size_t)b * N_DIM + row) * 512 + col;
                    __half2 hv; hv.x = __float2half(v0); hv.y = __float2half(v1);
                    *(__half2*)(g_H2hi + o) = hv;
                } else {
                    size_t o = ((size_t)b * H_DIM + row) * 512 + col;
                    __half h0, l0, h1, l1;
                    split2(v0, h0, l0);
                    split2(v1, h1, l1);
                    __half2 hv; hv.x = h0; hv.y = h1;
                    __half2 lv; lv.x = l0; lv.y = l1;
                    *(__half2*)(g_Mhi + o) = hv;
                    *(__half2*)(g_Mlo + o) = lv;
                }
            }
        }
    }
}

// ---------------- softmax / read ----------------
__global__ void k_softmax() {
    int b = blockIdx.x;
    int t = threadIdx.x;
    __shared__ float red[256];
    float m = -1e30f;
    for (int i = t; i < N_DIM; i += 256) m = fmaxf(m, g_logits[b * N_DIM + i]);
    red[t] = m;
    __syncthreads();
    for (int s = 128; s > 0; s >>= 1) {
        if (t < s) red[t] = fmaxf(red[t], red[t + s]);
        __syncthreads();
    }
    m = red[0];
    __syncthreads();
    float sum = 0.f;
    for (int i = t; i < N_DIM; i += 256) {
        float e = expf(g_logits[b * N_DIM + i] - m);
        g_a[b * N_DIM + i] = e;
        sum += e;
    }
    red[t] = sum;
    __syncthreads();
    for (int s = 128; s > 0; s >>= 1) {
        if (t < s) red[t] += red[t + s];
        __syncthreads();
    }
    float inv = 1.f / red[0];
    for (int i = t; i < N_DIM; i += 256) g_a[b * N_DIM + i] *= inv;
}

__global__ void k_read(const float* __restrict__ know, float* __restrict__ out) {
    int b = blockIdx.y;
    __shared__ __align__(16) float a_sh[N_DIM];
    for (int i = threadIdx.x; i < N_DIM; i += 256) a_sh[i] = g_a[b * N_DIM + i];
    __syncthreads();
    int warp = threadIdx.x >> 5, lane = threadIdx.x & 31;
    int kk = blockIdx.x * 8 + warp;
    const float* kr = know + ((size_t)b * KB_DIM + kk) * N_DIM;
    float s = 0.f;
    #pragma unroll
    for (int it = 0; it < 16; it++) {
        int n = it * 128 + lane * 4;
        float4 v = *(const float4*)(kr + n);
        float4 a = *(const float4*)&a_sh[n];
        s = fmaf(v.x, a.x, s);
        s = fmaf(v.y, a.y, s);
        s = fmaf(v.z, a.z, s);
        s = fmaf(v.w, a.w, s);
    }
    s = warp_sum(s);
    if (lane == 0) out[b * KB_DIM + kk] = s;
}

// ---------------- launch (kg<2> at position 4 so ncu profiles a 3-stage big GEMM) ------
extern "C" void kernel_launch(void* const* d_in, const int* in_sizes, int n_in,
                              void* d_out, int out_size) {
    const float* memory  = (const float*)d_in[0];
    const float* know    = (const float*)d_in[1];
    const float* control = (const float*)d_in[2];
    const float* masks   = (const float*)d_in[3];
    const float* W_mem   = (const float*)d_in[4];
    const float* b_mem   = (const float*)d_in[5];
    const float* W_kb    = (const float*)d_in[6];
    const float* b_kb    = (const float*)d_in[7];
    const float* W_cat   = (const float*)d_in[8];
    const float* b_cat   = (const float*)d_in[9];
    const float* W_cat2  = (const float*)d_in[10];
    const float* b_cat2  = (const float*)d_in[11];
    const float* W_attn  = (const float*)d_in[12];
    float* out = (float*)d_out;

    k_projmem<<<B_DIM, 512>>>(memory, masks, W_mem, b_mem, b_cat);           // 1
    k_wc_split<<<(B_DIM * H_DIM * H_DIM) / 256, 256>>>(W_cat, b_kb);         // 2
    k_split_wkbT<<<dim3(KB_DIM / 32, H_DIM / 32), 256>>>(W_kb);              // 3
    k_convT<<<dim3(N_DIM / 32, KB_DIM / 32, B_DIM), 256>>>(know);            // pre-4
    // NOTE: convT moved before the fold so the fold result is still ready in time.
    // weight fold: M_b = Wc_b @ W_kb   (512x512, K=512, per batch; 3-pass, 2-stage)
    kg<4><<<dim3(H_DIM / 128, H_DIM / 64, B_DIM), 256>>>(nullptr, nullptr, nullptr);  // 5
    // h = elu(k @ M_b^T + c_b)   (2-pass, 3-stage)
    kg<2><<<dim3(N_DIM / 128, H_DIM / 64, B_DIM), 256>>>(nullptr, nullptr, nullptr);  // 6
    k_split_w2<<<(H_DIM * H_DIM) / 256, 256>>>(W_cat2);                      // 7
    // logits += sum_g elu((h @ W2^T + b_cat2) * ctl) * W_attn   (2-pass, 3-stage, fused)
    kg<3><<<dim3(N_DIM / 128, H_DIM / 64, B_DIM), 256>>>(b_cat2, control, W_attn);    // 8
    k_softmax<<<B_DIM, 256>>>();                                             // 9
    k_read<<<dim3(KB_DIM / 8, B_DIM), 256>>>(know, out);                     // 10
}